// round 4
// baseline (speedup 1.0000x reference)
#include <cuda_runtime.h>
#include <math.h>
#include <float.h>

#define NROWS 32768
#define DIN   768
#define DLAT  256
#define RQ_DEPTH 4
#define KCODES 1024

#define WD       1e-5f   // d-gap window that triggers reference-rounding emulation
#define CS_STRIDE 260
#define CS_BUF    (16 * CS_STRIDE)

// ---------------- scratch (no allocations allowed) ----------------
__device__ float g_h1[NROWS * DLAT];
__device__ float g_res[NROWS * DLAT];
__device__ float g_q[NROWS * DLAT];
__device__ float g_cnorm[RQ_DEPTH * KCODES];

__device__ __forceinline__ float gelu_exact(float x) {
    float t = __fdiv_rn(x, 1.41421354f);
    float e = erff(t);
    float u = __fmul_rn(x, __fadd_rn(e, 1.0f));
    return __fmul_rn(u, 0.5f);
}

// =====================================================================
// SGEMM (unchanged from passing R3): BM=128, BN=64, BK=16, 256 thr, 8x4.
// EPI: 0 = bias; 1 = bias+GELU; 2 = bias, also C2=val, C3=0
// =====================================================================
template <int EPI>
__global__ __launch_bounds__(256, 4)
void sgemm_kernel(const float* __restrict__ A, const float* __restrict__ B,
                  const float* __restrict__ bias, float* __restrict__ C,
                  float* __restrict__ C2, float* __restrict__ C3,
                  int M, int N, int K)
{
    __shared__ float As[16][132];
    __shared__ float Bs[16][64];

    const int tid = threadIdx.x;
    const int tx = tid & 15;
    const int ty = tid >> 4;
    const int row0 = blockIdx.y * 128;
    const int col0 = blockIdx.x * 64;

    float acc[8][4];
#pragma unroll
    for (int i = 0; i < 8; i++)
#pragma unroll
        for (int j = 0; j < 4; j++) acc[i][j] = 0.0f;

    const int ar = tid >> 2;
    const int ac = (tid & 3) * 4;
    const int br = tid >> 4;
    const int bc = (tid & 15) * 4;

    for (int k0 = 0; k0 < K; k0 += 16) {
        float4 a0 = *(const float4*)(A + (size_t)(row0 + ar) * K + k0 + ac);
        float4 a1 = *(const float4*)(A + (size_t)(row0 + ar + 64) * K + k0 + ac);
        As[ac + 0][ar] = a0.x; As[ac + 1][ar] = a0.y;
        As[ac + 2][ar] = a0.z; As[ac + 3][ar] = a0.w;
        As[ac + 0][ar + 64] = a1.x; As[ac + 1][ar + 64] = a1.y;
        As[ac + 2][ar + 64] = a1.z; As[ac + 3][ar + 64] = a1.w;
        *(float4*)&Bs[br][bc] = *(const float4*)(B + (size_t)(k0 + br) * N + col0 + bc);
        __syncthreads();

#pragma unroll
        for (int k = 0; k < 16; k++) {
            float4 av0 = *(float4*)&As[k][ty * 8];
            float4 av1 = *(float4*)&As[k][ty * 8 + 4];
            float4 bv  = *(float4*)&Bs[k][tx * 4];
            float a[8] = {av0.x, av0.y, av0.z, av0.w, av1.x, av1.y, av1.z, av1.w};
            float b[4] = {bv.x, bv.y, bv.z, bv.w};
#pragma unroll
            for (int i = 0; i < 8; i++)
#pragma unroll
                for (int j = 0; j < 4; j++) acc[i][j] = __fmaf_rn(a[i], b[j], acc[i][j]);
        }
        __syncthreads();
    }

    float4 bb = *(const float4*)(bias + col0 + tx * 4);
#pragma unroll
    for (int i = 0; i < 8; i++) {
        int row = row0 + ty * 8 + i;
        float4 v;
        v.x = __fadd_rn(acc[i][0], bb.x); v.y = __fadd_rn(acc[i][1], bb.y);
        v.z = __fadd_rn(acc[i][2], bb.z); v.w = __fadd_rn(acc[i][3], bb.w);
        if (EPI == 1) {
            v.x = gelu_exact(v.x); v.y = gelu_exact(v.y);
            v.z = gelu_exact(v.z); v.w = gelu_exact(v.w);
        }
        size_t off = (size_t)row * N + col0 + tx * 4;
        *(float4*)(C + off) = v;
        if (EPI == 2) {
            *(float4*)(C2 + off) = v;
            float4 z = {0.f, 0.f, 0.f, 0.f};
            *(float4*)(C3 + off) = z;
        }
    }
}

// =====================================================================
// cnorm: ||c||^2, XLA GPU row-reduce order (strided-8 + shuffle tree)
// =====================================================================
__global__ void cnorm_kernel(const float* __restrict__ cb) {
    int gw = (blockIdx.x * blockDim.x + threadIdx.x) >> 5;
    int lane = threadIdx.x & 31;
    if (gw >= RQ_DEPTH * KCODES) return;
    const float* r = cb + (size_t)gw * DLAT;
    float s = 0.0f;
#pragma unroll
    for (int j = 0; j < 8; j++) {
        float v = r[lane + 32 * j];
        s = __fadd_rn(s, __fmul_rn(v, v));
    }
#pragma unroll
    for (int o = 16; o; o >>= 1)
        s = __fadd_rn(s, __shfl_down_sync(0xffffffffu, s, o));
    if (lane == 0) g_cnorm[gw] = s;
}

// =====================================================================
// RQ step v2: 64-row tile, 8x8 per-thread distance GEMM, single-sync
// double-buffered code chunks, warp-shuffle top-2, rescan-based tie path.
// =====================================================================
__device__ __forceinline__ void ldg_chunk(const float* __restrict__ cb, int u,
                                          int tid, float4* v) {
    int tile = u >> 4, kc = u & 15;
    const float* base = cb + ((size_t)(tile * 256 + (tid >> 2))) * DLAT
                           + kc * 16 + (tid & 3) * 4;
#pragma unroll
    for (int p = 0; p < 4; p++)
        v[p] = *(const float4*)(base + (size_t)p * 64 * DLAT);
}

__device__ __forceinline__ void sts_chunk(float* Csb, int tid, const float4* v) {
    int cg = tid >> 2;
    int kb = (tid & 3) * 4;
#pragma unroll
    for (int p = 0; p < 4; p++) {
        int code = cg + p * 64;
        Csb[(kb + 0) * CS_STRIDE + code] = v[p].x;
        Csb[(kb + 1) * CS_STRIDE + code] = v[p].y;
        Csb[(kb + 2) * CS_STRIDE + code] = v[p].z;
        Csb[(kb + 3) * CS_STRIDE + code] = v[p].w;
    }
}

__global__ __launch_bounds__(256, 2)
void rq2_kernel(const float* __restrict__ cb,      // [KCODES, DLAT]
                const float* __restrict__ cnorm,   // [KCODES]
                float* __restrict__ res, float* __restrict__ qsum,
                const float* __restrict__ latent,
                float* __restrict__ idx_out,
                float* __restrict__ qout)
{
    extern __shared__ float smem[];
    float* Rst = smem;                  // [k][row] 256*64
    float* Cs  = Rst + 16384;           // 2 * 16*260
    float* Cn  = Cs + 2 * CS_BUF;       // 1024

    __shared__ float gv1[64], gv2[64];
    __shared__ int gi1[64], gchosen[64], gflag[64], gcnt[64];
    __shared__ int gcand[64][8];

    const int tid  = threadIdx.x;
    const int lane = tid & 31;
    const int wrp  = tid >> 5;        // 0..7
    const int ty8  = wrp * 8;         // this warp's 8 rows
    const int tx8  = lane * 8;        // this lane's 8 codes within tile
    const int row0 = blockIdx.x * 64;

    // ---- setup: transposed residual tile, code norms, reduction state ----
    {
        int row = tid & 63;
        int cg  = tid >> 6;           // 0..3
        const float* src = res + (size_t)(row0 + row) * DLAT;
#pragma unroll
        for (int j = 0; j < 16; j++) {
            int c4 = cg * 16 + j;
            float4 v = *(const float4*)(src + c4 * 4);
            Rst[(c4 * 4 + 0) * 64 + row] = v.x;
            Rst[(c4 * 4 + 1) * 64 + row] = v.y;
            Rst[(c4 * 4 + 2) * 64 + row] = v.z;
            Rst[(c4 * 4 + 3) * 64 + row] = v.w;
        }
    }
#pragma unroll
    for (int m = 0; m < 4; m++) Cn[tid + m * 256] = cnorm[tid + m * 256];
    if (tid < 64) {
        gv1[tid] = FLT_MAX; gv2[tid] = FLT_MAX; gi1[tid] = 0; gcnt[tid] = 0;
    }

    // ---- pipeline prologue ----
    float4 v4[4];
    ldg_chunk(cb, 0, tid, v4);
    sts_chunk(Cs, tid, v4);
    ldg_chunk(cb, 1, tid, v4);
    __syncthreads();

    float acc[8][8];
#pragma unroll
    for (int i = 0; i < 8; i++)
#pragma unroll
        for (int j = 0; j < 8; j++) acc[i][j] = 0.0f;
    float cnr[8];

    for (int u = 0; u < 64; u++) {
        const int tile = u >> 4, kc = u & 15;
        if (kc == 0) {
            float4 c0 = *(const float4*)&Cn[tile * 256 + tx8];
            float4 c1 = *(const float4*)&Cn[tile * 256 + tx8 + 4];
            cnr[0] = c0.x; cnr[1] = c0.y; cnr[2] = c0.z; cnr[3] = c0.w;
            cnr[4] = c1.x; cnr[5] = c1.y; cnr[6] = c1.z; cnr[7] = c1.w;
        }
        const float* C = Cs + (u & 1) * CS_BUF;
#pragma unroll
        for (int k = 0; k < 16; k++) {
            const float* ra = &Rst[(kc * 16 + k) * 64 + ty8];
            float4 a0 = *(const float4*)ra;
            float4 a1 = *(const float4*)(ra + 4);
            float4 b0 = *(const float4*)&C[k * CS_STRIDE + tx8];
            float4 b1 = *(const float4*)&C[k * CS_STRIDE + tx8 + 4];
            float a[8] = {a0.x, a0.y, a0.z, a0.w, a1.x, a1.y, a1.z, a1.w};
            float b[8] = {b0.x, b0.y, b0.z, b0.w, b1.x, b1.y, b1.z, b1.w};
#pragma unroll
            for (int i = 0; i < 8; i++)
#pragma unroll
                for (int j = 0; j < 8; j++)
                    acc[i][j] = __fmaf_rn(a[i], b[j], acc[i][j]);
        }
        if (u < 63) sts_chunk(Cs + ((u + 1) & 1) * CS_BUF, tid, v4);
        if (kc == 15) {
            // fold this tile: per-thread top2 -> warp butterfly -> gtop merge
#pragma unroll
            for (int i = 0; i < 8; i++) {
                float v1 = FLT_MAX, v2 = FLT_MAX; int i1 = 0;
#pragma unroll
                for (int j = 0; j < 8; j++) {
                    float s = __fmaf_rn(-2.0f, acc[i][j], cnr[j]);
                    int code = tile * 256 + tx8 + j;
                    if (s < v1) { v2 = v1; v1 = s; i1 = code; }
                    else if (s < v2) { v2 = s; }
                    acc[i][j] = 0.0f;
                }
#pragma unroll
                for (int off = 16; off; off >>= 1) {
                    float ov1 = __shfl_xor_sync(0xffffffffu, v1, off);
                    int   oi1 = __shfl_xor_sync(0xffffffffu, i1, off);
                    float ov2 = __shfl_xor_sync(0xffffffffu, v2, off);
                    if (ov1 < v1 || (ov1 == v1 && oi1 < i1)) {
                        v2 = fminf(v1, ov2); v1 = ov1; i1 = oi1;
                    } else {
                        v2 = fminf(v2, ov1);
                    }
                }
                if (lane == 0) {
                    int r = ty8 + i;
                    float gv = gv1[r];
                    if (v1 < gv || (v1 == gv && i1 < gi1[r])) {
                        gv2[r] = fminf(gv, v2); gv1[r] = v1; gi1[r] = i1;
                    } else {
                        gv2[r] = fminf(gv2[r], v1);
                    }
                }
            }
        }
        if (u < 62) ldg_chunk(cb, u + 2, tid, v4);
        __syncthreads();
    }

    // ---- Phase A: flag near-ties, commit easy rows ----
    if (tid < 64) {
        float v1 = gv1[tid];
        int flag = (gv2[tid] - v1 < WD) ? 1 : 0;
        gflag[tid] = flag;
        if (!flag) {
            gchosen[tid] = gi1[tid];
            idx_out[row0 + tid] = (float)gi1[tid];
        }
    }
    __syncthreads();

    // ---- Phase B: warp-parallel rescan for flagged rows (candidate collect)
    for (int i = 0; i < 8; i++) {
        int r = ty8 + i;
        if (gflag[r]) {
            float v1 = gv1[r];
            for (int c = lane; c < KCODES; c += 32) {
                const float* crow = cb + (size_t)c * DLAT;
                float s0 = 0.f, s1 = 0.f, s2 = 0.f, s3 = 0.f;
                for (int k = 0; k < DLAT; k += 4) {
                    s0 = __fmaf_rn(Rst[(k + 0) * 64 + r], crow[k + 0], s0);
                    s1 = __fmaf_rn(Rst[(k + 1) * 64 + r], crow[k + 1], s1);
                    s2 = __fmaf_rn(Rst[(k + 2) * 64 + r], crow[k + 2], s2);
                    s3 = __fmaf_rn(Rst[(k + 3) * 64 + r], crow[k + 3], s3);
                }
                float dot = __fadd_rn(__fadd_rn(s0, s1), __fadd_rn(s2, s3));
                float s = __fmaf_rn(-2.0f, dot, Cn[c]);
                if (s <= v1 + 2.0f * WD) {
                    int pos = atomicAdd(&gcnt[r], 1);
                    if (pos < 8) gcand[r][pos] = c;
                }
            }
        }
    }
    __syncthreads();

    // ---- Phase C: reference-rounding emulation on candidates ----
    if (tid < 64 && gflag[tid]) {
        const int r = tid;
        int cl[9]; int n = 0;
        cl[n++] = gi1[r];
        int cc = gcnt[r]; if (cc > 8) cc = 8;
        for (int u2 = 0; u2 < cc; u2++) {
            int ix = gcand[r][u2];
            bool dup = false;
            for (int w2 = 0; w2 < n; w2++) if (cl[w2] == ix) dup = true;
            if (!dup) cl[n++] = ix;
        }
        // rn: emulate XLA warp row-reduce (strided-8 + tree)
        float lanes[32];
        for (int l = 0; l < 32; l++) {
            float s = 0.0f;
            for (int j = 0; j < 8; j++) {
                float v = Rst[(l + 32 * j) * 64 + r];
                s = __fadd_rn(s, __fmul_rn(v, v));
            }
            lanes[l] = s;
        }
        for (int o = 16; o; o >>= 1)
            for (int l = 0; l < o; l++)
                lanes[l] = __fadd_rn(lanes[l], lanes[l + o]);
        float rn = lanes[0];

        float bestd = FLT_MAX; int besti = 0x7fffffff;
        for (int u2 = 0; u2 < n; u2++) {
            int ix = cl[u2];
            const float* crow = cb + (size_t)ix * DLAT;
            float rc = 0.0f;
            for (int k = 0; k < DLAT; k++)
                rc = __fmaf_rn(Rst[k * 64 + r], crow[k], rc);
            float d = __fadd_rn(__fadd_rn(rn, __fmul_rn(-2.0f, rc)), Cn[ix]);
            if (d < bestd || (d == bestd && ix < besti)) { bestd = d; besti = ix; }
        }
        gchosen[r] = besti;
        idx_out[row0 + r] = (float)besti;
    }
    __syncthreads();

    // ---- Phase D: gather + residual/qsum update (+ STE on last depth) ----
#pragma unroll
    for (int m = 0; m < 16; m++) {
        int f = m * 256 + tid;
        int c4 = f & 63;
        int r  = f >> 6;
        int code = gchosen[r];
        size_t off = (size_t)(row0 + r) * DLAT + c4 * 4;
        float4 q = *(const float4*)(cb + (size_t)code * DLAT + c4 * 4);
        float4 rv = *(const float4*)(res + off);
        rv.x = __fadd_rn(rv.x, -q.x); rv.y = __fadd_rn(rv.y, -q.y);
        rv.z = __fadd_rn(rv.z, -q.z); rv.w = __fadd_rn(rv.w, -q.w);
        *(float4*)(res + off) = rv;
        float4 qs = *(const float4*)(qsum + off);
        qs.x = __fadd_rn(qs.x, q.x); qs.y = __fadd_rn(qs.y, q.y);
        qs.z = __fadd_rn(qs.z, q.z); qs.w = __fadd_rn(qs.w, q.w);
        *(float4*)(qsum + off) = qs;
        if (qout) {
            float4 lt = *(const float4*)(latent + off);
            float4 st;
            st.x = __fadd_rn(lt.x, __fadd_rn(qs.x, -lt.x));
            st.y = __fadd_rn(lt.y, __fadd_rn(qs.y, -lt.y));
            st.z = __fadd_rn(lt.z, __fadd_rn(qs.z, -lt.z));
            st.w = __fadd_rn(lt.w, __fadd_rn(qs.w, -lt.w));
            *(float4*)(qout + off) = st;
        }
    }
}

// =====================================================================
// launch
// =====================================================================
extern "C" void kernel_launch(void* const* d_in, const int* in_sizes, int n_in,
                              void* d_out, int out_size)
{
    const float* inputs = (const float*)d_in[0];
    const float* enc_w1 = (const float*)d_in[1];
    const float* enc_b1 = (const float*)d_in[2];
    const float* enc_w2 = (const float*)d_in[3];
    const float* enc_b2 = (const float*)d_in[4];
    const float* codebooks = (const float*)d_in[5];
    const float* dec_w1 = (const float*)d_in[6];
    const float* dec_b1 = (const float*)d_in[7];
    const float* dec_w2 = (const float*)d_in[8];
    const float* dec_b2 = (const float*)d_in[9];

    float* out = (float*)d_out;
    float* out_recon  = out;                                   // [N, 768]
    float* out_idx    = out_recon + (size_t)NROWS * DIN;       // [4, N]
    float* out_latent = out_idx + (size_t)RQ_DEPTH * NROWS;    // [N, 256]
    float* out_quant  = out_latent + (size_t)NROWS * DLAT;     // [N, 256]

    float *h1, *res, *q, *cn;
    cudaGetSymbolAddress((void**)&h1, g_h1);
    cudaGetSymbolAddress((void**)&res, g_res);
    cudaGetSymbolAddress((void**)&q, g_q);
    cudaGetSymbolAddress((void**)&cn, g_cnorm);

    const int RQ_SMEM = (16384 + 2 * CS_BUF + 1024) * 4;   // 102912 B
    cudaFuncSetAttribute(rq2_kernel, cudaFuncAttributeMaxDynamicSharedMemorySize, RQ_SMEM);

    // encoder
    sgemm_kernel<1><<<dim3(DLAT / 64, NROWS / 128), 256>>>(
        inputs, enc_w1, enc_b1, h1, nullptr, nullptr, NROWS, DLAT, DIN);
    sgemm_kernel<2><<<dim3(DLAT / 64, NROWS / 128), 256>>>(
        h1, enc_w2, enc_b2, out_latent, res, q, NROWS, DLAT, DLAT);

    // code norms (all depths, XLA reduce order)
    cnorm_kernel<<<(RQ_DEPTH * KCODES * 32) / 256, 256>>>(codebooks);

    // residual quantization
    for (int d = 0; d < RQ_DEPTH; d++) {
        rq2_kernel<<<NROWS / 64, 256, RQ_SMEM>>>(
            codebooks + (size_t)d * KCODES * DLAT,
            cn + (size_t)d * KCODES,
            res, q, out_latent,
            out_idx + (size_t)d * NROWS,
            (d == RQ_DEPTH - 1) ? out_quant : nullptr);
    }

    // decoder
    sgemm_kernel<1><<<dim3(DLAT / 64, NROWS / 128), 256>>>(
        out_quant, dec_w1, dec_b1, h1, nullptr, nullptr, NROWS, DLAT, DLAT);
    sgemm_kernel<0><<<dim3(DIN / 64, NROWS / 128), 256>>>(
        h1, dec_w2, dec_b2, out_recon, nullptr, nullptr, NROWS, DIN, DLAT);
}